// round 6
// baseline (speedup 1.0000x reference)
#include <cuda_runtime.h>

#define HIDDEN 8
#define RES 64
#define NBATCH 2048
#define TILE_H 16
#define SROWS 20            // TILE_H + 4 halo rows
#define SROW2 72            // smem row stride in float2 elements (cols 0..67 used)
#define SP_F2 (4 * SROWS * SROW2)        // channel-pair interleaved psi tile (float2 elems)
#define SP_FLOATS (SP_F2 * 2)            // 11520 floats
// packed param sections (float offsets, all even -> 8B aligned)
#define OFF_SWT2 (SP_FLOATS)             // 4cp x 5r x 8 pairs (padded) = 320 floats
#define OFF_SW2B (OFF_SWT2 + 320)        // 64 broadcast pairs = 128 floats
#define OFF_SW3B (OFF_SW2B + 128)        // 128 floats
#define OFF_SB1P (OFF_SW3B + 128)        // 4 pairs = 8 floats
#define OFF_SB2P (OFF_SB1P + 8)          // 8 pairs = 16 floats
#define OFF_SB3P (OFF_SB2P + 16)         // 16 floats
#define SMEM_FLOATS (OFF_SB3P + 16)
#define SMEM_BYTES (SMEM_FLOATS * 4)

typedef unsigned long long ull;

// D4-symmetrized, per-kernel-zero-mean 5x5 depthwise weights
__device__ float g_w[HIDDEN * 25];

__global__ void prep_weights_kernel(const float* __restrict__ filter1) {
    __shared__ float sw[HIDDEN * 25];
    int t = threadIdx.x;
    float wv = 0.f;
    int h = 0;
    if (t < 200) {
        h = t / 25;
        int idx = t % 25;
        int i = idx / 5, j = idx % 5;
        const float* f = filter1 + h * 25;
        float s = f[i*5 + j] + f[(4-i)*5 + j] + f[i*5 + (4-j)] + f[(4-i)*5 + (4-j)]
                + f[j*5 + i] + f[(4-j)*5 + i] + f[j*5 + (4-i)] + f[(4-j)*5 + (4-i)];
        wv = 0.125f * s;
        sw[t] = wv;
    }
    __syncthreads();
    if (t < 200) {
        float m = 0.f;
        #pragma unroll
        for (int k = 0; k < 25; k++) m += sw[h * 25 + k];
        g_w[t] = wv - m * (1.0f / 25.0f);
    }
}

// ---- packed f32x2 helpers (FFMA2 path: only reachable via PTX) ----
__device__ __forceinline__ ull pack2(float lo, float hi) {
    ull d; asm("mov.b64 %0, {%1, %2};" : "=l"(d) : "f"(lo), "f"(hi)); return d;
}
__device__ __forceinline__ void unpack2(ull d, float& lo, float& hi) {
    asm("mov.b64 {%0, %1}, %2;" : "=f"(lo), "=f"(hi) : "l"(d));
}
__device__ __forceinline__ ull fma2(ull a, ull b, ull c) {
    ull d; asm("fma.rn.f32x2 %0, %1, %2, %3;" : "=l"(d) : "l"(a), "l"(b), "l"(c)); return d;
}
__device__ __forceinline__ ull mul2(ull a, ull b) {
    ull d; asm("mul.rn.f32x2 %0, %1, %2;" : "=l"(d) : "l"(a), "l"(b)); return d;
}
// leaky_relu on a packed pair: 0.505*x + 0.495*|x|  (== x for x>0, 0.01x for x<0)
__device__ __forceinline__ ull lrelu2(ull x, ull c505, ull c495) {
    ull ax = x & 0x7FFFFFFF7FFFFFFFULL;
    return fma2(ax, c495, mul2(x, c505));
}
__device__ __forceinline__ float tanh_fast(float x) {
    float y;
    asm("tanh.approx.f32 %0, %1;" : "=f"(y) : "f"(x));
    return y;
}

__global__ __launch_bounds__(256, 3)
void ca_fused_kernel(const float* __restrict__ psi,
                     const float* __restrict__ bias1,
                     const float* __restrict__ w2,
                     const float* __restrict__ b2,
                     const float* __restrict__ w3,
                     const float* __restrict__ b3,
                     float* __restrict__ out)
{
    extern __shared__ __align__(16) float sm[];
    float* sp2f = sm;                       // [4cp][SROWS][SROW2] float2 (ch_even, ch_odd)
    ull*   sp2u = (ull*)sm;
    ull*   swt2 = (ull*)(sm + OFF_SWT2);    // conv wt pairs: [(cp*5+r)*8 + dx]
    ull*   sw2b = (ull*)(sm + OFF_SW2B);    // [i*8+o] = (w2[o][i], w2[o][i])
    ull*   sw3b = (ull*)(sm + OFF_SW3B);    // [i*8+o] = (w3[o][i], w3[o][i])
    ull*   sb1p = (ull*)(sm + OFF_SB1P);    // [cp] = (b1[2cp], b1[2cp+1])
    ull*   sb2p = (ull*)(sm + OFF_SB2P);    // [o]  = (b2[o], b2[o])
    ull*   sb3p = (ull*)(sm + OFF_SB3P);    // [o]  = (b3[o], b3[o])

    const int tid = threadIdx.x;
    const int b   = blockIdx.y;
    const int y0  = blockIdx.x * TILE_H;

    // ---- stage packed params ----
    if (tid < 160) {                        // conv weight pairs (rows padded to 8 slots)
        int cp = tid / 40, rem = tid % 40;
        int r = rem / 8, dx = rem % 8;
        float a = 0.f, bb = 0.f;
        if (dx < 5) {
            a  = g_w[(2*cp)     * 25 + r * 5 + dx];
            bb = g_w[(2*cp + 1) * 25 + r * 5 + dx];
        }
        swt2[tid] = pack2(a, bb);           // index == cp*40 + r*8 + dx
    }
    if (tid < 64) {
        int i = tid >> 3, o = tid & 7;
        sw2b[tid] = pack2(w2[o * 8 + i], w2[o * 8 + i]);
        sw3b[tid] = pack2(w3[o * 8 + i], w3[o * 8 + i]);
    }
    if (tid < 4)  sb1p[tid] = pack2(bias1[2*tid], bias1[2*tid + 1]);
    if (tid < 8)  { sb2p[tid] = pack2(b2[tid], b2[tid]); sb3p[tid] = pack2(b3[tid], b3[tid]); }

    // ---- zero x-halo columns (float2 cols 0,1,66,67) ----
    for (int k = tid; k < 4 * SROWS * 4; k += 256) {
        int c  = k & 3;
        int rr = k >> 2;                    // cp*SROWS + r
        int col = (c < 2) ? c : (64 + c);   // 0,1,66,67
        sp2u[rr * SROW2 + col] = 0ULL;
    }

    // ---- interior fill: channel-pair interleaved, float4 loads/stores ----
    const float* pb = psi + (size_t)b * (HIDDEN * RES * RES);
    for (int k = tid; k < 4 * SROWS * 16; k += 256) {
        int q  = k & 15;                     // float4 index within row
        int rr = k >> 4;                     // cp*SROWS + r
        int r  = rr % SROWS;
        int cp = rr / SROWS;
        int gy = y0 + r - 2;
        float4 a = make_float4(0.f,0.f,0.f,0.f), c = a;
        if ((unsigned)gy < RES) {
            a = *(const float4*)(pb + ((2*cp)   * RES + gy) * RES + q * 4);
            c = *(const float4*)(pb + ((2*cp+1) * RES + gy) * RES + q * 4);
        }
        float4* d = (float4*)(sp2f + (rr * SROW2 + q * 4 + 2) * 2);  // col = x+2
        d[0] = make_float4(a.x, c.x, a.y, c.y);
        d[1] = make_float4(a.z, c.z, a.w, c.w);
    }
    __syncthreads();

    const ull C505 = pack2(0.505f, 0.505f);
    const ull C495 = pack2(0.495f, 0.495f);

    // Each thread: 4 x-pixels of ONE output row, all 8 channels.
    const int tx = tid & 15;
    const int ry = tid >> 4;     // output row within tile (0..15)
    const int x0 = tx << 2;      // output x base (0..60)

    // ---- depthwise conv, channel-pair packed ----
    ull vp[8][2];                // conv activations, pixel-pair packed: vp[ch][pp]
    #pragma unroll
    for (int cp = 0; cp < 4; cp++) {
        ull bv = sb1p[cp];
        ull a0 = bv, a1 = bv, a2 = bv, a3 = bv;
        const ull* rowbase = sp2u + (cp * SROWS + ry) * SROW2 + x0;
        #pragma unroll
        for (int r = 0; r < 5; r++) {
            const ull* rp = rowbase + r * SROW2;
            ulonglong2 q0 = *(const ulonglong2*)(rp);
            ulonglong2 q1 = *(const ulonglong2*)(rp + 2);
            ulonglong2 q2 = *(const ulonglong2*)(rp + 4);
            ulonglong2 q3 = *(const ulonglong2*)(rp + 6);
            ull P0=q0.x, P1=q0.y, P2=q1.x, P3=q1.y, P4=q2.x, P5=q2.y, P6=q3.x, P7=q3.y;
            const ull* wr = swt2 + (cp * 5 + r) * 8;
            ulonglong2 wab = *(const ulonglong2*)(wr);
            ulonglong2 wcd = *(const ulonglong2*)(wr + 2);
            ull w4 = wr[4];
            a0 = fma2(wab.x, P0, a0); a1 = fma2(wab.x, P1, a1);
            a2 = fma2(wab.x, P2, a2); a3 = fma2(wab.x, P3, a3);
            a0 = fma2(wab.y, P1, a0); a1 = fma2(wab.y, P2, a1);
            a2 = fma2(wab.y, P3, a2); a3 = fma2(wab.y, P4, a3);
            a0 = fma2(wcd.x, P2, a0); a1 = fma2(wcd.x, P3, a1);
            a2 = fma2(wcd.x, P4, a2); a3 = fma2(wcd.x, P5, a3);
            a0 = fma2(wcd.y, P3, a0); a1 = fma2(wcd.y, P4, a1);
            a2 = fma2(wcd.y, P5, a2); a3 = fma2(wcd.y, P6, a3);
            a0 = fma2(w4,    P4, a0); a1 = fma2(w4,    P5, a1);
            a2 = fma2(w4,    P6, a2); a3 = fma2(w4,    P7, a3);
        }
        a0 = lrelu2(a0, C505, C495); a1 = lrelu2(a1, C505, C495);
        a2 = lrelu2(a2, C505, C495); a3 = lrelu2(a3, C505, C495);
        // transpose: (ch-pair packed per pixel) -> (pixel-pair packed per channel)
        float e0,f0, e1,f1, e2,f2, e3,f3;
        unpack2(a0, e0, f0); unpack2(a1, e1, f1);
        unpack2(a2, e2, f2); unpack2(a3, e3, f3);
        vp[2*cp    ][0] = pack2(e0, e1); vp[2*cp    ][1] = pack2(e2, e3);
        vp[2*cp + 1][0] = pack2(f0, f1); vp[2*cp + 1][1] = pack2(f2, f3);
    }

    // ---- GEMM1 (8x8), pixel-pair packed ----
    ull z2[8][2];
    #pragma unroll
    for (int o = 0; o < 8; o++) { ull bv = sb2p[o]; z2[o][0] = bv; z2[o][1] = bv; }
    #pragma unroll
    for (int i = 0; i < 8; i++) {
        #pragma unroll
        for (int o = 0; o < 8; o++) {
            ull w = sw2b[i * 8 + o];
            z2[o][0] = fma2(w, vp[i][0], z2[o][0]);
            z2[o][1] = fma2(w, vp[i][1], z2[o][1]);
        }
    }
    #pragma unroll
    for (int o = 0; o < 8; o++) {
        z2[o][0] = lrelu2(z2[o][0], C505, C495);
        z2[o][1] = lrelu2(z2[o][1], C505, C495);
    }

    // ---- GEMM2 (8x8), pixel-pair packed ----
    ull hp[8][2];
    #pragma unroll
    for (int o = 0; o < 8; o++) { ull bv = sb3p[o]; hp[o][0] = bv; hp[o][1] = bv; }
    #pragma unroll
    for (int i = 0; i < 8; i++) {
        #pragma unroll
        for (int o = 0; o < 8; o++) {
            ull w = sw3b[i * 8 + o];
            hp[o][0] = fma2(w, z2[i][0], hp[o][0]);
            hp[o][1] = fma2(w, z2[i][1], hp[o][1]);
        }
    }

    // ---- residual + tanh + store ----
    float* ob = out + (size_t)b * (HIDDEN * RES * RES);
    const int gy = y0 + ry;
    #pragma unroll
    for (int cp = 0; cp < 4; cp++) {
        // psi residual: pixels x0..x0+3, both channels of this pair, from smem
        const float4* rp = (const float4*)(sp2f + ((cp * SROWS + ry + 2) * SROW2 + x0 + 2) * 2);
        float4 rA = rp[0];   // (e[x0], o[x0], e[x0+1], o[x0+1])
        float4 rB = rp[1];   // (e[x0+2], o[x0+2], e[x0+3], o[x0+3])
        int oe = 2 * cp, oo = 2 * cp + 1;
        float h0, h1, h2, h3;
        unpack2(hp[oe][0], h0, h1); unpack2(hp[oe][1], h2, h3);
        float4 res;
        res.x = tanh_fast(rA.x + h0); res.y = tanh_fast(rA.z + h1);
        res.z = tanh_fast(rB.x + h2); res.w = tanh_fast(rB.z + h3);
        *(float4*)(ob + (oe * RES + gy) * RES + x0) = res;
        unpack2(hp[oo][0], h0, h1); unpack2(hp[oo][1], h2, h3);
        res.x = tanh_fast(rA.y + h0); res.y = tanh_fast(rA.w + h1);
        res.z = tanh_fast(rB.y + h2); res.w = tanh_fast(rB.w + h3);
        *(float4*)(ob + (oo * RES + gy) * RES + x0) = res;
    }
}

extern "C" void kernel_launch(void* const* d_in, const int* in_sizes, int n_in,
                              void* d_out, int out_size) {
    const float* psi     = (const float*)d_in[0];
    const float* filter1 = (const float*)d_in[1];
    const float* bias1   = (const float*)d_in[2];
    const float* w2      = (const float*)d_in[3];
    const float* b2      = (const float*)d_in[4];
    const float* w3      = (const float*)d_in[5];
    const float* b3      = (const float*)d_in[6];
    float* out = (float*)d_out;

    cudaFuncSetAttribute(ca_fused_kernel,
                         cudaFuncAttributeMaxDynamicSharedMemorySize, SMEM_BYTES);

    prep_weights_kernel<<<1, 256>>>(filter1);

    dim3 grid(RES / TILE_H, NBATCH);
    ca_fused_kernel<<<grid, 256, SMEM_BYTES>>>(psi, bias1, w2, b2, w3, b3, out);
}